// round 2
// baseline (speedup 1.0000x reference)
#include <cuda_runtime.h>
#include <cuda_bf16.h>

#define NN 50000
#define EE 800000
#define NB_SCAN 49   // ceil(NN/1024)

// ---------------- scratch (static device globals; no allocation) ----------------
__device__ int   g_is64;
__device__ int   g_deg[NN];
__device__ float g_dis[NN];
__device__ int   g_off[NN + 1];
__device__ int   g_cur[NN];
__device__ int   g_bsum[64];
__device__ int   g_bpre[64];
__device__ int   g_row[EE];
__device__ float g_scaled[NN * 64];   // dis[n] * (X @ Wb)
__device__ float g_w[NN * 32];        // X @ Wc + bc
__device__ float g_h1[NN * 128];      // layer-1 output
__device__ float g_p0[NN * 2];        // h2 . Wcls[0:128]
__device__ float g_p1[NN * 2];        // h2 . Wcls[128:256]

// ---------------- edge-index dtype detection + accessors ----------------
// int64 storage: odd int32 words are the zero high halves (all values < 50000).
// int32 storage: odd words are random node indices -> essentially never all zero.
__global__ void detect_kernel(const int* __restrict__ w) {
    int bad = 0;
    for (int i = 1 + 2 * threadIdx.x; i < 1024; i += 64) bad |= w[i];
    unsigned any = __ballot_sync(0xffffffffu, bad != 0);
    if (threadIdx.x == 0) g_is64 = (any == 0) ? 1 : 0;
}

__device__ __forceinline__ int edge_at(const void* ei, int idx, int is64) {
    if (is64) return (int)((const long long*)ei)[idx];
    return ((const int*)ei)[idx];
}

// ---------------- preprocessing ----------------
__global__ void zero_kernel() {
    int i = blockIdx.x * blockDim.x + threadIdx.x;
    if (i < NN) { g_deg[i] = 0; g_cur[i] = 0; }
}

__global__ void count_kernel(const void* __restrict__ ei) {
    int e = blockIdx.x * blockDim.x + threadIdx.x;
    if (e < EE) {
        int c = edge_at(ei, EE + e, g_is64);
        if ((unsigned)c < NN) atomicAdd(&g_deg[c], 1);
    }
}

__global__ void dis_kernel() {
    int i = blockIdx.x * blockDim.x + threadIdx.x;
    if (i < NN) g_dis[i] = rsqrtf((float)(g_deg[i] + 1));  // +1 self loop, always > 0
}

// inclusive scan within 1024-blocks -> g_off[i+1], block sums -> g_bsum
__global__ void scanA_kernel() {
    __shared__ int s[1024];
    int tid = threadIdx.x;
    int i = blockIdx.x * 1024 + tid;
    int v = (i < NN) ? g_deg[i] : 0;
    s[tid] = v;
    __syncthreads();
    for (int off = 1; off < 1024; off <<= 1) {
        int t = (tid >= off) ? s[tid - off] : 0;
        __syncthreads();
        s[tid] += t;
        __syncthreads();
    }
    if (i < NN) g_off[i + 1] = s[tid];
    if (tid == 1023) g_bsum[blockIdx.x] = s[1023];
}

__global__ void scanB_kernel() {
    if (threadIdx.x == 0) {
        int acc = 0;
        for (int b = 0; b < NB_SCAN; b++) { int t = g_bsum[b]; g_bpre[b] = acc; acc += t; }
        g_off[0] = 0;
    }
}

__global__ void scanC_kernel() {
    int i = blockIdx.x * blockDim.x + threadIdx.x;
    if (i < NN) g_off[i + 1] += g_bpre[i >> 10];
}

__global__ void fill_kernel(const void* __restrict__ ei) {
    int e = blockIdx.x * blockDim.x + threadIdx.x;
    if (e < EE) {
        int is64 = g_is64;
        int c = edge_at(ei, EE + e, is64);
        int r = edge_at(ei, e, is64);
        if ((unsigned)c < NN && (unsigned)r < NN) {
            int p = atomicAdd(&g_cur[c], 1);
            g_row[g_off[c] + p] = r;
        }
    }
}

// ---------------- GEMM: [NN,128] @ [128, 64|32] -> scaled (dis-weighted), w (+bc) ----------------
// block: 128 threads, 32 nodes per block, micro-tile 4 nodes x 6 cols, k split into 2 stages of 64
template <bool USE_H1>
__global__ void gemm_kernel(const float* __restrict__ xin,
                            const float* __restrict__ Wb,
                            const float* __restrict__ Wc,
                            const float* __restrict__ bc) {
    __shared__ float Wsh[64 * 96];
    __shared__ float xs[32 * 65];
    const float* X = USE_H1 ? (const float*)g_h1 : xin;

    int tid = threadIdx.x;
    int cg = tid & 15, ng = tid >> 4;
    int nb = blockIdx.x * 32;
    int cb = cg * 6;
    float acc[4][6];
#pragma unroll
    for (int j = 0; j < 4; j++)
#pragma unroll
        for (int c = 0; c < 6; c++) acc[j][c] = 0.f;

    for (int s = 0; s < 2; s++) {
        int k0 = s * 64;
        for (int i = tid; i < 64 * 96; i += 128) {
            int r = i / 96, c = i - r * 96;
            float v = (c < 64) ? Wb[(k0 + r) * 64 + c] : Wc[(k0 + r) * 32 + (c - 64)];
            Wsh[r * 96 + c] = v;
        }
        for (int i = tid; i < 32 * 64; i += 128) {
            int nn = i >> 6, k = i & 63;
            int gn = nb + nn;
            xs[nn * 65 + k] = (gn < NN) ? X[gn * 128 + k0 + k] : 0.f;
        }
        __syncthreads();
#pragma unroll 8
        for (int k = 0; k < 64; k++) {
            float wv[6], xv[4];
#pragma unroll
            for (int c = 0; c < 6; c++) wv[c] = Wsh[k * 96 + cb + c];
#pragma unroll
            for (int j = 0; j < 4; j++) xv[j] = xs[(ng * 4 + j) * 65 + k];
#pragma unroll
            for (int j = 0; j < 4; j++)
#pragma unroll
                for (int c = 0; c < 6; c++) acc[j][c] += xv[j] * wv[c];
        }
        __syncthreads();
    }

    for (int j = 0; j < 4; j++) {
        int gn = nb + ng * 4 + j;
        if (gn >= NN) continue;
        float di = g_dis[gn];
#pragma unroll
        for (int c = 0; c < 6; c++) {
            int gc = cb + c;
            if (gc < 64) g_scaled[gn * 64 + gc] = di * acc[j][c];
            else         g_w[gn * 32 + (gc - 64)] = acc[j][c] + bc[gc - 64];
        }
    }
}

// ---------------- aggregate + combine (+ optional classifier projection) ----------------
// one warp per node; 8 warps/block
template <bool L2>
__global__ void agg_kernel(const float* __restrict__ bias,
                           const float* __restrict__ Wcls) {
    __shared__ float sh[8][64];
    __shared__ float shw[8][32];
    int warp = threadIdx.x >> 5, lane = threadIdx.x & 31;
    int i = blockIdx.x * 8 + warp;
    if (i >= NN) return;

    shw[warp][lane] = g_w[i * 32 + lane];
    float a0 = g_scaled[i * 64 + lane];          // self loop (dis folded in)
    float a1 = g_scaled[i * 64 + 32 + lane];
    int e0 = g_off[i], e1 = g_off[i + 1];
    for (int e = e0; e < e1; e++) {
        int j = __ldg(&g_row[e]);
        a0 += __ldg(&g_scaled[j * 64 + lane]);
        a1 += __ldg(&g_scaled[j * 64 + 32 + lane]);
    }
    float di = g_dis[i];
    sh[warp][lane] = a0 * di;
    sh[warp][lane + 32] = a1 * di;
    __syncwarp();

    float p00 = 0.f, p01 = 0.f, p10 = 0.f, p11 = 0.f;
#pragma unroll
    for (int q = 0; q < 4; q++) {
        int o = lane + 32 * q;
        int h = o >> 4, f = o & 15;
        float v = bias[o];
#pragma unroll
        for (int b = 0; b < 4; b++) v += shw[warp][h * 4 + b] * sh[warp][b * 16 + f];
        if (!L2) {
            v = fmaxf(v, 0.f);
            g_h1[i * 128 + o] = v;
        } else {
            p00 += v * __ldg(&Wcls[o * 2]);
            p01 += v * __ldg(&Wcls[o * 2 + 1]);
            p10 += v * __ldg(&Wcls[(128 + o) * 2]);
            p11 += v * __ldg(&Wcls[(128 + o) * 2 + 1]);
        }
    }
    if (L2) {
#pragma unroll
        for (int s = 16; s; s >>= 1) {
            p00 += __shfl_xor_sync(0xffffffffu, p00, s);
            p01 += __shfl_xor_sync(0xffffffffu, p01, s);
            p10 += __shfl_xor_sync(0xffffffffu, p10, s);
            p11 += __shfl_xor_sync(0xffffffffu, p11, s);
        }
        if (lane == 0) {
            g_p0[i * 2] = p00; g_p0[i * 2 + 1] = p01;
            g_p1[i * 2] = p10; g_p1[i * 2 + 1] = p11;
        }
    }
}

// ---------------- edge classifier: out[e] = p0[src] + p1[dst] + bcls ----------------
__global__ void edge_kernel(const void* __restrict__ ei,
                            const float* __restrict__ bcls,
                            float* __restrict__ out) {
    int e = blockIdx.x * blockDim.x + threadIdx.x;
    if (e < EE) {
        int is64 = g_is64;
        int s = edge_at(ei, e, is64);
        int d = edge_at(ei, EE + e, is64);
        float ax = 0.f, ay = 0.f, bx = 0.f, by = 0.f;
        if ((unsigned)s < NN) { ax = g_p0[s * 2]; ay = g_p0[s * 2 + 1]; }
        if ((unsigned)d < NN) { bx = g_p1[d * 2]; by = g_p1[d * 2 + 1]; }
        out[e * 2]     = ax + bx + bcls[0];
        out[e * 2 + 1] = ay + by + bcls[1];
    }
}

// ---------------- launch ----------------
extern "C" void kernel_launch(void* const* d_in, const int* in_sizes, int n_in,
                              void* d_out, int out_size) {
    const float* x    = (const float*)d_in[0];
    const void*  ei   = (const void*)d_in[1];
    const float* Wb1  = (const float*)d_in[2];
    const float* Wc1  = (const float*)d_in[3];
    const float* bc1  = (const float*)d_in[4];
    const float* b1   = (const float*)d_in[5];
    const float* Wb2  = (const float*)d_in[6];
    const float* Wc2  = (const float*)d_in[7];
    const float* bc2  = (const float*)d_in[8];
    const float* b2   = (const float*)d_in[9];
    const float* Wcls = (const float*)d_in[10];
    const float* bcls = (const float*)d_in[11];
    float* out = (float*)d_out;

    const int TPB = 256;
    int gN = (NN + TPB - 1) / TPB;
    int gE = (EE + TPB - 1) / TPB;

    detect_kernel<<<1, 32>>>((const int*)ei);
    zero_kernel<<<gN, TPB>>>();
    count_kernel<<<gE, TPB>>>(ei);
    dis_kernel<<<gN, TPB>>>();
    scanA_kernel<<<NB_SCAN, 1024>>>();
    scanB_kernel<<<1, 32>>>();
    scanC_kernel<<<gN, TPB>>>();
    fill_kernel<<<gE, TPB>>>(ei);

    int gGemm = (NN + 31) / 32;
    int gAgg  = (NN + 7) / 8;

    gemm_kernel<false><<<gGemm, 128>>>(x, Wb1, Wc1, bc1);
    agg_kernel<false><<<gAgg, 256>>>(b1, Wcls);
    gemm_kernel<true><<<gGemm, 128>>>(nullptr, Wb2, Wc2, bc2);
    agg_kernel<true><<<gAgg, 256>>>(b2, Wcls);
    edge_kernel<<<gE, TPB>>>(ei, bcls, out);
}

// round 3
// speedup vs baseline: 1.1202x; 1.1202x over previous
#include <cuda_runtime.h>
#include <cuda_bf16.h>

#define NN 50000
#define EE 800000
#define NB_SCAN 49   // ceil(NN/1024)

typedef unsigned long long ull;

// ---------------- scratch (static device globals; no allocation) ----------------
__device__ int   g_is64;
__device__ int   g_deg[NN];
__device__ float g_dis[NN];
__device__ int   g_off[NN + 1];
__device__ int   g_cur[NN];
__device__ int   g_bsum[64];
__device__ int   g_bpre[64];
__device__ int   g_row[EE];
__device__ float g_scaled[NN * 64];   // dis[n] * (X @ Wb)
__device__ float g_w[NN * 32];        // X @ Wc + bc
__device__ float g_h1[NN * 128];      // layer-1 output
__device__ float g_p0[NN * 2];        // h2 . Wcls[0:128]
__device__ float g_p1[NN * 2];        // h2 . Wcls[128:256]

// ---------------- f32x2 helpers ----------------
__device__ __forceinline__ ull pack2(float a) {
    ull r; asm("mov.b64 %0, {%1, %1};" : "=l"(r) : "f"(a)); return r;
}
__device__ __forceinline__ void fma2(ull& d, ull a, ull b) {
    asm("fma.rn.f32x2 %0, %1, %2, %0;" : "+l"(d) : "l"(a), "l"(b));
}
__device__ __forceinline__ void unpack2(ull v, float& lo, float& hi) {
    asm("mov.b64 {%0, %1}, %2;" : "=f"(lo), "=f"(hi) : "l"(v));
}

// ---------------- edge-index dtype detection + accessors ----------------
// int64 storage: odd int32 words are the zero high halves (all values < 50000).
// int32 storage: odd words are random node indices -> essentially never all zero.
__global__ void detect_kernel(const int* __restrict__ w) {
    int bad = 0;
    for (int i = 1 + 2 * threadIdx.x; i < 1024; i += 64) bad |= w[i];
    unsigned any = __ballot_sync(0xffffffffu, bad != 0);
    if (threadIdx.x == 0) g_is64 = (any == 0) ? 1 : 0;
}

__device__ __forceinline__ int edge_at(const void* ei, int idx, int is64) {
    if (is64) return (int)((const long long*)ei)[idx];
    return ((const int*)ei)[idx];
}

// ---------------- preprocessing ----------------
__global__ void zero_kernel() {
    int i = blockIdx.x * blockDim.x + threadIdx.x;
    if (i < NN) { g_deg[i] = 0; g_cur[i] = 0; }
}

__global__ void count_kernel(const void* __restrict__ ei) {
    int e = blockIdx.x * blockDim.x + threadIdx.x;
    if (e < EE) {
        int c = edge_at(ei, EE + e, g_is64);
        if ((unsigned)c < NN) atomicAdd(&g_deg[c], 1);
    }
}

// inclusive scan within 1024-blocks -> g_off[i+1], block sums -> g_bsum
__global__ void scanA_kernel() {
    __shared__ int s[1024];
    int tid = threadIdx.x;
    int i = blockIdx.x * 1024 + tid;
    int v = (i < NN) ? g_deg[i] : 0;
    s[tid] = v;
    __syncthreads();
    for (int off = 1; off < 1024; off <<= 1) {
        int t = (tid >= off) ? s[tid - off] : 0;
        __syncthreads();
        s[tid] += t;
        __syncthreads();
    }
    if (i < NN) g_off[i + 1] = s[tid];
    if (tid == 1023) g_bsum[blockIdx.x] = s[1023];
}

__global__ void scanB_kernel() {
    if (threadIdx.x == 0) {
        int acc = 0;
        for (int b = 0; b < NB_SCAN; b++) { int t = g_bsum[b]; g_bpre[b] = acc; acc += t; }
        g_off[0] = 0;
    }
}

// scan finalize + dis (fused: both per-node, deg is final here)
__global__ void scanC_kernel() {
    int i = blockIdx.x * blockDim.x + threadIdx.x;
    if (i < NN) {
        g_off[i + 1] += g_bpre[i >> 10];
        g_dis[i] = rsqrtf((float)(g_deg[i] + 1));   // +1 self loop, always > 0
    }
}

__global__ void fill_kernel(const void* __restrict__ ei) {
    int e = blockIdx.x * blockDim.x + threadIdx.x;
    if (e < EE) {
        int is64 = g_is64;
        int c = edge_at(ei, EE + e, is64);
        int r = edge_at(ei, e, is64);
        if ((unsigned)c < NN && (unsigned)r < NN) {
            int p = atomicAdd(&g_cur[c], 1);
            g_row[g_off[c] + p] = r;
        }
    }
}

// ---------------- GEMM: [NN,128] @ [128, 64|32] via packed f32x2 FMA ----------------
// block 128 threads, 32 nodes. Thread (cg=tid&15, ng=tid>>4) computes nodes
// ng*4..+3 x col-pairs {cg, cg+16, cg+32} (float2 columns). k split in 2 stages of 64.
template <bool USE_H1>
__global__ void gemm_kernel(const float* __restrict__ xin,
                            const float* __restrict__ Wb,
                            const float* __restrict__ Wc,
                            const float* __restrict__ bc) {
    __shared__ float Wsh[64 * 96];   // 24 KB
    __shared__ float xs[32 * 65];    // 8.3 KB
    const float* X = USE_H1 ? (const float*)g_h1 : xin;

    int tid = threadIdx.x;
    int cg = tid & 15, ng = tid >> 4;
    int nb = blockIdx.x * 32;
    ull acc[4][3];
#pragma unroll
    for (int j = 0; j < 4; j++)
#pragma unroll
        for (int c = 0; c < 3; c++) acc[j][c] = 0ull;

    for (int s = 0; s < 2; s++) {
        int k0 = s * 64;
        for (int i = tid; i < 64 * 96; i += 128) {
            int r = i / 96, c = i - r * 96;
            float v = (c < 64) ? Wb[(k0 + r) * 64 + c] : Wc[(k0 + r) * 32 + (c - 64)];
            Wsh[r * 96 + c] = v;
        }
        for (int i = tid; i < 32 * 64; i += 128) {
            int nn = i >> 6, k = i & 63;
            int gn = nb + nn;
            xs[nn * 65 + k] = (gn < NN) ? X[gn * 128 + k0 + k] : 0.f;
        }
        __syncthreads();
#pragma unroll 8
        for (int k = 0; k < 64; k++) {
            const float* wrow = &Wsh[k * 96];
            ull wv[3];
            wv[0] = *(const ull*)&wrow[2 * cg];
            wv[1] = *(const ull*)&wrow[2 * cg + 32];
            wv[2] = *(const ull*)&wrow[2 * cg + 64];
            ull xv[4];
#pragma unroll
            for (int j = 0; j < 4; j++) xv[j] = pack2(xs[(ng * 4 + j) * 65 + k]);
#pragma unroll
            for (int j = 0; j < 4; j++)
#pragma unroll
                for (int c = 0; c < 3; c++) fma2(acc[j][c], xv[j], wv[c]);
        }
        __syncthreads();
    }

    // epilogue: c=0 -> scaled cols {2cg, 2cg+1}; c=1 -> scaled cols {2cg+32, 2cg+33};
    //           c=2 -> w cols {2cg, 2cg+1}
    float bclo = bc[2 * cg], bchi = bc[2 * cg + 1];
#pragma unroll
    for (int j = 0; j < 4; j++) {
        int gn = nb + ng * 4 + j;
        if (gn >= NN) continue;
        float di = g_dis[gn];
        float lo, hi;
        unpack2(acc[j][0], lo, hi);
        g_scaled[gn * 64 + 2 * cg]      = di * lo;
        g_scaled[gn * 64 + 2 * cg + 1]  = di * hi;
        unpack2(acc[j][1], lo, hi);
        g_scaled[gn * 64 + 2 * cg + 32] = di * lo;
        g_scaled[gn * 64 + 2 * cg + 33] = di * hi;
        unpack2(acc[j][2], lo, hi);
        g_w[gn * 32 + 2 * cg]     = lo + bclo;
        g_w[gn * 32 + 2 * cg + 1] = hi + bchi;
    }
}

// ---------------- aggregate + combine (+ optional classifier projection) ----------------
// one warp per node; 8 warps/block; lane gathers one float2 (8B) per neighbor row
template <bool L2K>
__global__ void agg_kernel(const float* __restrict__ bias,
                           const float* __restrict__ Wcls) {
    __shared__ float sh[8][64];
    __shared__ float shw[8][32];
    int warp = threadIdx.x >> 5, lane = threadIdx.x & 31;
    int i = blockIdx.x * 8 + warp;
    if (i >= NN) return;

    shw[warp][lane] = g_w[i * 32 + lane];
    const float2* S = (const float2*)g_scaled;
    float2 a = __ldg(&S[i * 32 + lane]);          // self loop (dis folded in)
    int e0 = g_off[i], e1 = g_off[i + 1];
    int e = e0;
    for (; e + 4 <= e1; e += 4) {
        int j0 = __ldg(&g_row[e]);
        int j1 = __ldg(&g_row[e + 1]);
        int j2 = __ldg(&g_row[e + 2]);
        int j3 = __ldg(&g_row[e + 3]);
        float2 b0 = __ldg(&S[j0 * 32 + lane]);
        float2 b1 = __ldg(&S[j1 * 32 + lane]);
        float2 b2 = __ldg(&S[j2 * 32 + lane]);
        float2 b3 = __ldg(&S[j3 * 32 + lane]);
        a.x += (b0.x + b1.x) + (b2.x + b3.x);
        a.y += (b0.y + b1.y) + (b2.y + b3.y);
    }
    for (; e < e1; e++) {
        int j = __ldg(&g_row[e]);
        float2 b = __ldg(&S[j * 32 + lane]);
        a.x += b.x; a.y += b.y;
    }
    float di = g_dis[i];
    sh[warp][2 * lane]     = a.x * di;
    sh[warp][2 * lane + 1] = a.y * di;
    __syncwarp();

    float p00 = 0.f, p01 = 0.f, p10 = 0.f, p11 = 0.f;
#pragma unroll
    for (int q = 0; q < 4; q++) {
        int o = lane + 32 * q;
        int h = o >> 4, f = o & 15;
        float v = bias[o];
#pragma unroll
        for (int b = 0; b < 4; b++) v += shw[warp][h * 4 + b] * sh[warp][b * 16 + f];
        if (!L2K) {
            v = fmaxf(v, 0.f);
            g_h1[i * 128 + o] = v;
        } else {
            p00 += v * __ldg(&Wcls[o * 2]);
            p01 += v * __ldg(&Wcls[o * 2 + 1]);
            p10 += v * __ldg(&Wcls[(128 + o) * 2]);
            p11 += v * __ldg(&Wcls[(128 + o) * 2 + 1]);
        }
    }
    if (L2K) {
#pragma unroll
        for (int s = 16; s; s >>= 1) {
            p00 += __shfl_xor_sync(0xffffffffu, p00, s);
            p01 += __shfl_xor_sync(0xffffffffu, p01, s);
            p10 += __shfl_xor_sync(0xffffffffu, p10, s);
            p11 += __shfl_xor_sync(0xffffffffu, p11, s);
        }
        if (lane == 0) {
            g_p0[i * 2] = p00; g_p0[i * 2 + 1] = p01;
            g_p1[i * 2] = p10; g_p1[i * 2 + 1] = p11;
        }
    }
}

// ---------------- edge classifier: out[e] = p0[src] + p1[dst] + bcls ----------------
__global__ void edge_kernel(const void* __restrict__ ei,
                            const float* __restrict__ bcls,
                            float* __restrict__ out) {
    int e = blockIdx.x * blockDim.x + threadIdx.x;
    if (e < EE) {
        int is64 = g_is64;
        int s = edge_at(ei, e, is64);
        int d = edge_at(ei, EE + e, is64);
        float ax = 0.f, ay = 0.f, bx = 0.f, by = 0.f;
        if ((unsigned)s < NN) { float2 a = __ldg((const float2*)&g_p0[s * 2]); ax = a.x; ay = a.y; }
        if ((unsigned)d < NN) { float2 b = __ldg((const float2*)&g_p1[d * 2]); bx = b.x; by = b.y; }
        float2 o; o.x = ax + bx + bcls[0]; o.y = ay + by + bcls[1];
        *(float2*)&out[e * 2] = o;
    }
}

// ---------------- launch ----------------
extern "C" void kernel_launch(void* const* d_in, const int* in_sizes, int n_in,
                              void* d_out, int out_size) {
    const float* x    = (const float*)d_in[0];
    const void*  ei   = (const void*)d_in[1];
    const float* Wb1  = (const float*)d_in[2];
    const float* Wc1  = (const float*)d_in[3];
    const float* bc1  = (const float*)d_in[4];
    const float* b1   = (const float*)d_in[5];
    const float* Wb2  = (const float*)d_in[6];
    const float* Wc2  = (const float*)d_in[7];
    const float* bc2  = (const float*)d_in[8];
    const float* b2   = (const float*)d_in[9];
    const float* Wcls = (const float*)d_in[10];
    const float* bcls = (const float*)d_in[11];
    float* out = (float*)d_out;

    const int TPB = 256;
    int gN = (NN + TPB - 1) / TPB;
    int gE = (EE + TPB - 1) / TPB;

    detect_kernel<<<1, 32>>>((const int*)ei);
    zero_kernel<<<gN, TPB>>>();
    count_kernel<<<gE, TPB>>>(ei);
    scanA_kernel<<<NB_SCAN, 1024>>>();
    scanB_kernel<<<1, 32>>>();
    scanC_kernel<<<gN, TPB>>>();
    fill_kernel<<<gE, TPB>>>(ei);

    int gGemm = (NN + 31) / 32;
    int gAgg  = (NN + 7) / 8;

    gemm_kernel<false><<<gGemm, 128>>>(x, Wb1, Wc1, bc1);
    agg_kernel<false><<<gAgg, 256>>>(b1, Wcls);
    gemm_kernel<true><<<gGemm, 128>>>(nullptr, Wb2, Wc2, bc2);
    agg_kernel<true><<<gAgg, 256>>>(b2, Wcls);
    edge_kernel<<<gE, TPB>>>(ei, bcls, out);
}

// round 4
// speedup vs baseline: 1.1317x; 1.0103x over previous
#include <cuda_runtime.h>
#include <cuda_bf16.h>

#define NN 50000
#define EE 800000
#define NB_SCAN 49   // ceil(NN/1024)

typedef unsigned long long ull;

// ---------------- scratch (static device globals; no allocation) ----------------
__device__ int   g_is64;
__device__ int   g_deg[NN];
__device__ float g_dis[NN];
__device__ int   g_off[NN + 1];
__device__ int   g_cur[NN];
__device__ int   g_bsum[64];
__device__ int   g_row[EE];
__device__ float g_scaled[NN * 64];   // dis[n] * (X @ Wb)
__device__ float g_w[NN * 32];        // X @ Wc + bc
__device__ float g_h1[NN * 128];      // layer-1 output
__device__ float g_p0[NN * 2];        // h2 . Wcls[0:128]
__device__ float g_p1[NN * 2];        // h2 . Wcls[128:256]

// ---------------- f32x2 helpers ----------------
__device__ __forceinline__ ull pack2(float a) {
    ull r; asm("mov.b64 %0, {%1, %1};" : "=l"(r) : "f"(a)); return r;
}
__device__ __forceinline__ void fma2(ull& d, ull a, ull b) {
    asm("fma.rn.f32x2 %0, %1, %2, %0;" : "+l"(d) : "l"(a), "l"(b));
}
__device__ __forceinline__ void unpack2(ull v, float& lo, float& hi) {
    asm("mov.b64 {%0, %1}, %2;" : "=f"(lo), "=f"(hi) : "l"(v));
}

__device__ __forceinline__ int edge_at(const void* ei, int idx, int is64) {
    if (is64) return (int)((const long long*)ei)[idx];
    return ((const int*)ei)[idx];
}

// ---------------- zero + edge-dtype detect (fused) ----------------
// int64 storage: odd int32 words are the zero high halves (all values < 50000).
// int32 storage: odd words are random node indices -> essentially never all zero.
__global__ void zero_kernel(const int* __restrict__ w) {
    int i = blockIdx.x * blockDim.x + threadIdx.x;
    if (i < NN) { g_deg[i] = 0; g_cur[i] = 0; }
    if (blockIdx.x == 0 && threadIdx.x < 32) {
        int bad = 0;
        for (int k = 1 + 2 * threadIdx.x; k < 1024; k += 64) bad |= w[k];
        unsigned any = __ballot_sync(0xffffffffu, bad != 0);
        if (threadIdx.x == 0) g_is64 = (any == 0) ? 1 : 0;
    }
}

__global__ void count_kernel(const void* __restrict__ ei) {
    int e = blockIdx.x * blockDim.x + threadIdx.x;
    if (e < EE) {
        int c = edge_at(ei, EE + e, g_is64);
        if ((unsigned)c < NN) atomicAdd(&g_deg[c], 1);
    }
}

// inclusive scan within 1024-blocks (warp-shuffle based) -> g_off[i+1], sums -> g_bsum
__global__ void scanA_kernel() {
    __shared__ int wsum[32];
    int tid = threadIdx.x, lane = tid & 31, wp = tid >> 5;
    int i = blockIdx.x * 1024 + tid;
    int v = (i < NN) ? g_deg[i] : 0;
    int s = v;
#pragma unroll
    for (int o = 1; o < 32; o <<= 1) {
        int t = __shfl_up_sync(0xffffffffu, s, o);
        if (lane >= o) s += t;
    }
    if (lane == 31) wsum[wp] = s;
    __syncthreads();
    if (wp == 0) {
        int ws = wsum[lane];
        int t2 = ws;
#pragma unroll
        for (int o = 1; o < 32; o <<= 1) {
            int t = __shfl_up_sync(0xffffffffu, t2, o);
            if (lane >= o) t2 += t;
        }
        wsum[lane] = t2 - ws;   // exclusive
    }
    __syncthreads();
    s += wsum[wp];
    if (i < NN) g_off[i + 1] = s;
    if (tid == 1023) g_bsum[blockIdx.x] = s;
}

// finalize scan (each block redundantly prefixes the 49 block sums) + dis
__global__ void scanC_kernel() {
    __shared__ int s_pre[64];
    int tid = threadIdx.x;
    if (tid < 32) {
        int v0 = (tid < NB_SCAN) ? g_bsum[tid] : 0;
        int s0 = v0;
#pragma unroll
        for (int o = 1; o < 32; o <<= 1) {
            int t = __shfl_up_sync(0xffffffffu, s0, o);
            if (tid >= o) s0 += t;
        }
        s_pre[tid] = s0 - v0;
        int tot0 = __shfl_sync(0xffffffffu, s0, 31);
        int idx = 32 + tid;
        int v1 = (idx < NB_SCAN) ? g_bsum[idx] : 0;
        int s1 = v1;
#pragma unroll
        for (int o = 1; o < 32; o <<= 1) {
            int t = __shfl_up_sync(0xffffffffu, s1, o);
            if (tid >= o) s1 += t;
        }
        s_pre[idx] = tot0 + s1 - v1;
    }
    __syncthreads();
    int i = blockIdx.x * blockDim.x + tid;
    if (i < NN) {
        g_off[i + 1] += s_pre[i >> 10];
        g_dis[i] = rsqrtf((float)(g_deg[i] + 1));   // +1 self loop, always > 0
    }
    if (i == 0) g_off[0] = 0;
}

__global__ void fill_kernel(const void* __restrict__ ei) {
    int e = blockIdx.x * blockDim.x + threadIdx.x;
    if (e < EE) {
        int is64 = g_is64;
        int c = edge_at(ei, EE + e, is64);
        int r = edge_at(ei, e, is64);
        if ((unsigned)c < NN && (unsigned)r < NN) {
            int p = atomicAdd(&g_cur[c], 1);
            g_row[g_off[c] + p] = r;
        }
    }
}

// ---------------- GEMM: [NN,128] @ [128, 64|32] via packed f32x2 FMA ----------------
// block 128 threads, 64 nodes. Thread (cg=tid&15, ng=tid>>4) computes nodes
// ng*8..+7 x col-pairs {cg, cg+16, cg+32} (float2 columns). k split in 2 stages of 64.
template <bool USE_H1>
__global__ void gemm_kernel(const float* __restrict__ xin,
                            const float* __restrict__ Wb,
                            const float* __restrict__ Wc,
                            const float* __restrict__ bc) {
    __shared__ float Wsh[64 * 96];   // 24 KB
    __shared__ float xs[64 * 65];    // 16.6 KB
    const float* X = USE_H1 ? (const float*)g_h1 : xin;

    int tid = threadIdx.x;
    int cg = tid & 15, ng = tid >> 4;
    int nb = blockIdx.x * 64;
    ull acc[8][3];
#pragma unroll
    for (int j = 0; j < 8; j++)
#pragma unroll
        for (int c = 0; c < 3; c++) acc[j][c] = 0ull;

    for (int s = 0; s < 2; s++) {
        int k0 = s * 64;
        for (int i = tid; i < 64 * 96; i += 128) {
            int r = i / 96, c = i - r * 96;
            float v = (c < 64) ? Wb[(k0 + r) * 64 + c] : Wc[(k0 + r) * 32 + (c - 64)];
            Wsh[r * 96 + c] = v;
        }
        for (int i = tid; i < 64 * 64; i += 128) {
            int nn = i >> 6, k = i & 63;
            int gn = nb + nn;
            xs[nn * 65 + k] = (gn < NN) ? X[gn * 128 + k0 + k] : 0.f;
        }
        __syncthreads();
#pragma unroll 4
        for (int k = 0; k < 64; k++) {
            const float* wrow = &Wsh[k * 96];
            ull wv[3];
            wv[0] = *(const ull*)&wrow[2 * cg];
            wv[1] = *(const ull*)&wrow[2 * cg + 32];
            wv[2] = *(const ull*)&wrow[2 * cg + 64];
            ull xv[8];
#pragma unroll
            for (int j = 0; j < 8; j++) xv[j] = pack2(xs[(ng * 8 + j) * 65 + k]);
#pragma unroll
            for (int j = 0; j < 8; j++)
#pragma unroll
                for (int c = 0; c < 3; c++) fma2(acc[j][c], xv[j], wv[c]);
        }
        __syncthreads();
    }

    // epilogue: c=0 -> scaled cols {2cg,2cg+1}; c=1 -> scaled {2cg+32,+33}; c=2 -> w {2cg,+1}
    float bclo = bc[2 * cg], bchi = bc[2 * cg + 1];
#pragma unroll
    for (int j = 0; j < 8; j++) {
        int gn = nb + ng * 8 + j;
        if (gn >= NN) continue;
        float di = g_dis[gn];
        float lo, hi;
        unpack2(acc[j][0], lo, hi);
        float2 o0; o0.x = di * lo; o0.y = di * hi;
        *(float2*)&g_scaled[gn * 64 + 2 * cg] = o0;
        unpack2(acc[j][1], lo, hi);
        float2 o1; o1.x = di * lo; o1.y = di * hi;
        *(float2*)&g_scaled[gn * 64 + 2 * cg + 32] = o1;
        unpack2(acc[j][2], lo, hi);
        float2 o2; o2.x = lo + bclo; o2.y = hi + bchi;
        *(float2*)&g_w[gn * 32 + 2 * cg] = o2;
    }
}

// ---------------- aggregate + combine (+ optional classifier projection) ----------------
// one warp per node; 8 warps/block; lane gathers one float2 (8B) per neighbor row
template <bool L2K>
__global__ void agg_kernel(const float* __restrict__ bias,
                           const float* __restrict__ Wcls) {
    __shared__ float sh[8][64];
    __shared__ float shw[8][32];
    int warp = threadIdx.x >> 5, lane = threadIdx.x & 31;
    int i = blockIdx.x * 8 + warp;
    if (i >= NN) return;

    shw[warp][lane] = g_w[i * 32 + lane];
    const float2* S = (const float2*)g_scaled;
    float2 a = __ldg(&S[i * 32 + lane]);          // self loop (dis folded in)
    int e0 = g_off[i], e1 = g_off[i + 1];
    int e = e0;
    for (; e + 4 <= e1; e += 4) {
        int j0 = __ldg(&g_row[e]);
        int j1 = __ldg(&g_row[e + 1]);
        int j2 = __ldg(&g_row[e + 2]);
        int j3 = __ldg(&g_row[e + 3]);
        float2 b0 = __ldg(&S[j0 * 32 + lane]);
        float2 b1 = __ldg(&S[j1 * 32 + lane]);
        float2 b2 = __ldg(&S[j2 * 32 + lane]);
        float2 b3 = __ldg(&S[j3 * 32 + lane]);
        a.x += (b0.x + b1.x) + (b2.x + b3.x);
        a.y += (b0.y + b1.y) + (b2.y + b3.y);
    }
    for (; e < e1; e++) {
        int j = __ldg(&g_row[e]);
        float2 b = __ldg(&S[j * 32 + lane]);
        a.x += b.x; a.y += b.y;
    }
    float di = g_dis[i];
    sh[warp][2 * lane]     = a.x * di;
    sh[warp][2 * lane + 1] = a.y * di;
    __syncwarp();

    float p00 = 0.f, p01 = 0.f, p10 = 0.f, p11 = 0.f;
#pragma unroll
    for (int q = 0; q < 4; q++) {
        int o = lane + 32 * q;
        int h = o >> 4, f = o & 15;
        float v = bias[o];
#pragma unroll
        for (int b = 0; b < 4; b++) v += shw[warp][h * 4 + b] * sh[warp][b * 16 + f];
        if (!L2K) {
            v = fmaxf(v, 0.f);
            g_h1[i * 128 + o] = v;
        } else {
            p00 += v * __ldg(&Wcls[o * 2]);
            p01 += v * __ldg(&Wcls[o * 2 + 1]);
            p10 += v * __ldg(&Wcls[(128 + o) * 2]);
            p11 += v * __ldg(&Wcls[(128 + o) * 2 + 1]);
        }
    }
    if (L2K) {
#pragma unroll
        for (int s = 16; s; s >>= 1) {
            p00 += __shfl_xor_sync(0xffffffffu, p00, s);
            p01 += __shfl_xor_sync(0xffffffffu, p01, s);
            p10 += __shfl_xor_sync(0xffffffffu, p10, s);
            p11 += __shfl_xor_sync(0xffffffffu, p11, s);
        }
        if (lane == 0) {
            g_p0[i * 2] = p00; g_p0[i * 2 + 1] = p01;
            g_p1[i * 2] = p10; g_p1[i * 2 + 1] = p11;
        }
    }
}

// ---------------- edge classifier: out[e] = p0[src] + p1[dst] + bcls ----------------
__global__ void edge_kernel(const void* __restrict__ ei,
                            const float* __restrict__ bcls,
                            float* __restrict__ out) {
    int e = blockIdx.x * blockDim.x + threadIdx.x;
    if (e < EE) {
        int is64 = g_is64;
        int s = edge_at(ei, e, is64);
        int d = edge_at(ei, EE + e, is64);
        float ax = 0.f, ay = 0.f, bx = 0.f, by = 0.f;
        if ((unsigned)s < NN) { float2 a = __ldg((const float2*)&g_p0[s * 2]); ax = a.x; ay = a.y; }
        if ((unsigned)d < NN) { float2 b = __ldg((const float2*)&g_p1[d * 2]); bx = b.x; by = b.y; }
        float2 o; o.x = ax + bx + bcls[0]; o.y = ay + by + bcls[1];
        *(float2*)&out[e * 2] = o;
    }
}

// ---------------- launch ----------------
extern "C" void kernel_launch(void* const* d_in, const int* in_sizes, int n_in,
                              void* d_out, int out_size) {
    const float* x    = (const float*)d_in[0];
    const void*  ei   = (const void*)d_in[1];
    const float* Wb1  = (const float*)d_in[2];
    const float* Wc1  = (const float*)d_in[3];
    const float* bc1  = (const float*)d_in[4];
    const float* b1   = (const float*)d_in[5];
    const float* Wb2  = (const float*)d_in[6];
    const float* Wc2  = (const float*)d_in[7];
    const float* bc2  = (const float*)d_in[8];
    const float* b2   = (const float*)d_in[9];
    const float* Wcls = (const float*)d_in[10];
    const float* bcls = (const float*)d_in[11];
    float* out = (float*)d_out;

    const int TPB = 256;
    int gN = (NN + TPB - 1) / TPB;
    int gE = (EE + TPB - 1) / TPB;

    zero_kernel<<<gN, TPB>>>((const int*)ei);
    count_kernel<<<gE, TPB>>>(ei);
    scanA_kernel<<<NB_SCAN, 1024>>>();
    scanC_kernel<<<gN, TPB>>>();
    fill_kernel<<<gE, TPB>>>(ei);

    int gGemm = (NN + 63) / 64;
    int gAgg  = (NN + 7) / 8;

    gemm_kernel<false><<<gGemm, 128>>>(x, Wb1, Wc1, bc1);
    agg_kernel<false><<<gAgg, 256>>>(b1, Wcls);
    gemm_kernel<true><<<gGemm, 128>>>(nullptr, Wb2, Wc2, bc2);
    agg_kernel<true><<<gAgg, 256>>>(b2, Wcls);
    edge_kernel<<<gE, TPB>>>(ei, bcls, out);
}